// round 3
// baseline (speedup 1.0000x reference)
#include <cuda_runtime.h>

#define BATCH  16384
#define HIDDEN 1024
#define EMB    512
#define KAUG   (HIDDEN + EMB)   // 1536
#define NOPS   8

// ---------------- scratch (static device allocations only) ----------------
__device__ int   g_cnt[NOPS];
__device__ int   g_off[NOPS];
__device__ int   g_cur[NOPS];
__device__ int   g_idx[BATCH];                       // token ids sorted by expert
__device__ float g_h[(size_t)BATCH * HIDDEN];        // layer-1 activations (sorted order)

// ---------------- tiny routing kernels ----------------
__global__ void k_zero() {
    if (threadIdx.x < NOPS) { g_cnt[threadIdx.x] = 0; g_cur[threadIdx.x] = 0; }
}

__global__ void k_count(const int* __restrict__ ops) {
    int t = blockIdx.x * blockDim.x + threadIdx.x;
    if (t < BATCH) atomicAdd(&g_cnt[ops[t]], 1);
}

__global__ void k_scan() {
    // single thread, 8 elements
    int s = 0;
    for (int i = 0; i < NOPS; i++) { g_off[i] = s; s += g_cnt[i]; g_cur[i] = 0; }
}

__global__ void k_scatter(const int* __restrict__ ops) {
    int t = blockIdx.x * blockDim.x + threadIdx.x;
    if (t < BATCH) {
        int e = ops[t];
        int p = g_off[e] + atomicAdd(&g_cur[e], 1);
        g_idx[p] = t;
    }
}

// ---------------- grouped SGEMM: 128x128 block tile, BK=8, 256 thr, 8x8/thr ----------------
// LAYER 1: A = [x | op_emb] gathered rows (K=1536), out = relu(A@W1[e]+b1[e]) -> g_h (sorted)
// LAYER 2: A = g_h rows      (K=1024),             out = relu(A@W2[e]+b2[e]) -> d_out (scatter by token)
template <int LAYER>
__global__ __launch_bounds__(256, 2)
void k_gemm(const float* __restrict__ x,
            const float* __restrict__ op_emb,
            const float* __restrict__ W,      // [NOPS, KD, HIDDEN] row-major
            const float* __restrict__ bias,   // [NOPS, HIDDEN]
            float* __restrict__ out)
{
    constexpr int KD = (LAYER == 1) ? KAUG : HIDDEN;

    const int e   = blockIdx.z;
    const int cnt = g_cnt[e];
    const int m0  = blockIdx.x * 128;
    if (m0 >= cnt) return;                    // early-exit for unused tiles
    const int off = g_off[e];
    const int n0  = blockIdx.y * 128;
    const int tid = threadIdx.x;

    __shared__ float As[8][128];
    __shared__ float Bs[8][128];
    __shared__ int   s_tok[128];

    if (tid < 128) {
        int m = m0 + tid;
        s_tok[tid] = (m < cnt) ? g_idx[off + m] : -1;
    }
    __syncthreads();

    // A-load mapping: 2 threads per row, each loads float4 (8 k per row-tile)
    const int arow = tid >> 1;                // 0..127
    const int akk  = (tid & 1) * 4;           // 0 or 4
    // B-load mapping: kk = tid/32 (0..7), 4 consecutive n per thread
    const int bkk  = tid >> 5;
    const int bn   = (tid & 31) * 4;

    // compute mapping: 16x16 thread grid, 8x8 micro-tile
    const int rb = (tid >> 4) * 8;            // row base within tile
    const int cb = (tid & 15) * 8;            // col base within tile

    float acc[8][8];
#pragma unroll
    for (int i = 0; i < 8; i++)
#pragma unroll
        for (int j = 0; j < 8; j++) acc[i][j] = 0.f;

    const float* Wb = W + (size_t)e * KD * HIDDEN;

    for (int k0 = 0; k0 < KD; k0 += 8) {
        // ---- load A tile (128 x 8) ----
        float4 av = make_float4(0.f, 0.f, 0.f, 0.f);
        {
            int m = m0 + arow;
            int k = k0 + akk;
            if (m < cnt) {
                if (LAYER == 1) {
                    if (k < HIDDEN) {
                        int t = s_tok[arow];
                        av = *reinterpret_cast<const float4*>(&x[(size_t)t * HIDDEN + k]);
                    } else {
                        av = *reinterpret_cast<const float4*>(&op_emb[e * EMB + (k - HIDDEN)]);
                    }
                } else {
                    av = *reinterpret_cast<const float4*>(&g_h[(size_t)(off + m) * HIDDEN + k]);
                }
            }
        }
        // ---- load B tile (8 x 128) ----
        float4 bv = *reinterpret_cast<const float4*>(
            &Wb[(size_t)(k0 + bkk) * HIDDEN + n0 + bn]);

        As[akk + 0][arow] = av.x;
        As[akk + 1][arow] = av.y;
        As[akk + 2][arow] = av.z;
        As[akk + 3][arow] = av.w;
        *reinterpret_cast<float4*>(&Bs[bkk][bn]) = bv;
        __syncthreads();

        // ---- compute ----
#pragma unroll
        for (int kk = 0; kk < 8; kk++) {
            float a[8], b[8];
            float4 a0 = *reinterpret_cast<const float4*>(&As[kk][rb]);
            float4 a1 = *reinterpret_cast<const float4*>(&As[kk][rb + 4]);
            float4 b0 = *reinterpret_cast<const float4*>(&Bs[kk][cb]);
            float4 b1 = *reinterpret_cast<const float4*>(&Bs[kk][cb + 4]);
            a[0]=a0.x; a[1]=a0.y; a[2]=a0.z; a[3]=a0.w;
            a[4]=a1.x; a[5]=a1.y; a[6]=a1.z; a[7]=a1.w;
            b[0]=b0.x; b[1]=b0.y; b[2]=b0.z; b[3]=b0.w;
            b[4]=b1.x; b[5]=b1.y; b[6]=b1.z; b[7]=b1.w;
#pragma unroll
            for (int i = 0; i < 8; i++)
#pragma unroll
                for (int j = 0; j < 8; j++)
                    acc[i][j] += a[i] * b[j];
        }
        __syncthreads();
    }

    // ---- epilogue: bias + relu, store ----
    float bb[8];
#pragma unroll
    for (int j = 0; j < 8; j++) bb[j] = bias[e * HIDDEN + n0 + cb + j];

#pragma unroll
    for (int i = 0; i < 8; i++) {
        int m = m0 + rb + i;
        if (m >= cnt) continue;
        float* dst;
        if (LAYER == 1) {
            dst = &g_h[(size_t)(off + m) * HIDDEN + n0 + cb];
        } else {
            int t = s_tok[rb + i];
            dst = &out[(size_t)t * HIDDEN + n0 + cb];
        }
#pragma unroll
        for (int j = 0; j < 8; j++) {
            float v = acc[i][j] + bb[j];
            dst[j] = v > 0.f ? v : 0.f;
        }
    }
}

// ---------------- launch ----------------
extern "C" void kernel_launch(void* const* d_in, const int* in_sizes, int n_in,
                              void* d_out, int out_size)
{
    const float* x      = (const float*)d_in[0];
    const int*   ops    = (const int*)  d_in[1];
    const float* op_emb = (const float*)d_in[2];
    const float* W1     = (const float*)d_in[3];
    const float* b1     = (const float*)d_in[4];
    const float* W2     = (const float*)d_in[5];
    const float* b2     = (const float*)d_in[6];
    float* out = (float*)d_out;

    k_zero<<<1, 32>>>();
    k_count<<<BATCH / 256, 256>>>(ops);
    k_scan<<<1, 1>>>();
    k_scatter<<<BATCH / 256, 256>>>(ops);

    dim3 grid(BATCH / 128, HIDDEN / 128, NOPS);   // early-exit prunes unused m-tiles
    k_gemm<1><<<grid, 256>>>(x, op_emb, W1, b1, nullptr);
    k_gemm<2><<<grid, 256>>>(x, op_emb, W2, b2, out);
}

// round 16
// speedup vs baseline: 2.2732x; 2.2732x over previous
#include <cuda_runtime.h>
#include <cuda_bf16.h>
#include <cstdint>

// R16: identical artifact to R11/R15 submissions — both prior rounds died to
// infra (device-busy / container-failed) before any launch; first real bench
// of the mma.sync grouped-GEMM path.

#define BATCH   16384
#define HIDDEN  1024
#define EMB     512
#define KAUG    1536
#define NOPS    8
#define MAXS    136              // max m-tiles: 128 + 8 partials
#define STAGES  4
#define ROWB    80               // padded smem row stride (32 bf16 -> 80B), conflict-free ldmatrix
#define TILEB   (128*ROWB)       // 10240 per operand per stage
#define STAGEB  (2*TILEB)        // 20480
#define SMEM_GEMM (STAGES*STAGEB) // 81920

// ---------------- static device scratch ----------------
__device__ int g_cnt[NOPS], g_off[NOPS], g_cur[NOPS], g_idx[BATCH];
__device__ int g_tilebase[NOPS], g_slot_e[MAXS], g_slot_m0[MAXS], g_nslots;

__device__ __align__(16) unsigned short g_ahi[(size_t)MAXS*128*KAUG];
__device__ __align__(16) unsigned short g_alo[(size_t)MAXS*128*KAUG];
__device__ __align__(16) unsigned short g_hhi[(size_t)MAXS*128*HIDDEN];
__device__ __align__(16) unsigned short g_hlo[(size_t)MAXS*128*HIDDEN];
__device__ __align__(16) unsigned short g_b1hi[(size_t)NOPS*HIDDEN*KAUG];
__device__ __align__(16) unsigned short g_b1lo[(size_t)NOPS*HIDDEN*KAUG];
__device__ __align__(16) unsigned short g_b2hi[(size_t)NOPS*HIDDEN*HIDDEN];
__device__ __align__(16) unsigned short g_b2lo[(size_t)NOPS*HIDDEN*HIDDEN];

// ---------------- helpers ----------------
__device__ __forceinline__ uint32_t smem_u32(const void* p) {
    uint32_t a;
    asm("{ .reg .u64 t; cvta.to.shared.u64 t, %1; cvt.u32.u64 %0, t; }" : "=r"(a) : "l"(p));
    return a;
}
__device__ __forceinline__ void cp16(uint32_t s, const void* g) {
    asm volatile("cp.async.cg.shared.global [%0], [%1], 16;" :: "r"(s), "l"(g) : "memory");
}
__device__ __forceinline__ void cp_commit() {
    asm volatile("cp.async.commit_group;" ::: "memory");
}
template <int N>
__device__ __forceinline__ void cp_wait() {
    asm volatile("cp.async.wait_group %0;" :: "n"(N) : "memory");
}
__device__ __forceinline__ void ldm4(uint32_t* r, uint32_t addr) {
    asm volatile("ldmatrix.sync.aligned.m8n8.x4.shared.b16 {%0,%1,%2,%3}, [%4];"
                 : "=r"(r[0]), "=r"(r[1]), "=r"(r[2]), "=r"(r[3]) : "r"(addr));
}
__device__ __forceinline__ void mma16816(float* c, const uint32_t* a, uint32_t b0, uint32_t b1) {
    asm volatile(
        "mma.sync.aligned.m16n8k16.row.col.f32.bf16.bf16.f32 "
        "{%0,%1,%2,%3}, {%4,%5,%6,%7}, {%8,%9}, {%0,%1,%2,%3};"
        : "+f"(c[0]), "+f"(c[1]), "+f"(c[2]), "+f"(c[3])
        : "r"(a[0]), "r"(a[1]), "r"(a[2]), "r"(a[3]), "r"(b0), "r"(b1));
}
__device__ __forceinline__ void split2(float v, unsigned short& h, unsigned short& l) {
    __nv_bfloat16 hb = __float2bfloat16(v);
    __nv_bfloat16 lb = __float2bfloat16(v - __bfloat162float(hb));
    h = __bfloat16_as_ushort(hb);
    l = __bfloat16_as_ushort(lb);
}

// ---------------- routing ----------------
__global__ void k_zero() {
    if (threadIdx.x < NOPS) { g_cnt[threadIdx.x] = 0; g_cur[threadIdx.x] = 0; }
}
__global__ void k_count(const int* __restrict__ ops) {
    int t = blockIdx.x * blockDim.x + threadIdx.x;
    if (t < BATCH) atomicAdd(&g_cnt[ops[t]], 1);
}
__global__ void k_scan() {
    int s = 0, slot = 0;
    for (int e = 0; e < NOPS; e++) {
        g_off[e] = s; s += g_cnt[e]; g_cur[e] = 0;
        g_tilebase[e] = slot;
        int nt = (g_cnt[e] + 127) >> 7;
        for (int i = 0; i < nt; i++) { g_slot_e[slot] = e; g_slot_m0[slot] = i << 7; slot++; }
    }
    g_nslots = slot;
}
__global__ void k_scatter(const int* __restrict__ ops) {
    int t = blockIdx.x * blockDim.x + threadIdx.x;
    if (t < BATCH) {
        int e = ops[t];
        int p = g_off[e] + atomicAdd(&g_cur[e], 1);
        g_idx[p] = t;
    }
}

// ---------------- A-aug conversion: gather + hi/lo split, row-major [slot*128, 1536] ----------------
__global__ __launch_bounds__(256) void k_aconv(const float* __restrict__ x,
                                               const float* __restrict__ emb) {
    int s = blockIdx.x;
    if (s >= g_nslots) return;
    int e = g_slot_e[s], m0 = g_slot_m0[s], off = g_off[e], cnt = g_cnt[e];
    int tid = threadIdx.x;
#pragma unroll 4
    for (int i = 0; i < 96; i++) {                 // 128 rows * 192 granules(8f) / 256 thr
        int G = i * 256 + tid;
        int row = G / 192, gc = G - row * 192;
        int k = gc * 8;
        float v[8];
        int m = m0 + row;
        if (m < cnt) {
            const float* src;
            if (k < HIDDEN) { int t = g_idx[off + m]; src = x + (size_t)t * HIDDEN + k; }
            else            { src = emb + e * EMB + (k - HIDDEN); }
            float4 f0 = *(const float4*)src;
            float4 f1 = *(const float4*)(src + 4);
            v[0]=f0.x; v[1]=f0.y; v[2]=f0.z; v[3]=f0.w;
            v[4]=f1.x; v[5]=f1.y; v[6]=f1.z; v[7]=f1.w;
        } else {
#pragma unroll
            for (int q = 0; q < 8; q++) v[q] = 0.f;
        }
        uint32_t hw[4], lw[4];
#pragma unroll
        for (int q = 0; q < 4; q++) {
            unsigned short h0, l0, h1, l1;
            split2(v[2*q],   h0, l0);
            split2(v[2*q+1], h1, l1);
            hw[q] = (uint32_t)h0 | ((uint32_t)h1 << 16);
            lw[q] = (uint32_t)l0 | ((uint32_t)l1 << 16);
        }
        size_t o = ((size_t)s * 128 + row) * KAUG + k;
        *(uint4*)&g_ahi[o] = make_uint4(hw[0], hw[1], hw[2], hw[3]);
        *(uint4*)&g_alo[o] = make_uint4(lw[0], lw[1], lw[2], lw[3]);
    }
}

// ---------------- weight conversion: transpose [K,N]->[N,K] + hi/lo split ----------------
template <int KD>
__global__ __launch_bounds__(256) void k_wconv(const float* __restrict__ W) {
    __shared__ float sN[64][65];
    int k0 = blockIdx.x << 6, n0 = blockIdx.y << 6, e = blockIdx.z;
    const float* Wb = W + (size_t)e * KD * HIDDEN;
    int tid = threadIdx.x;
#pragma unroll
    for (int i = 0; i < 16; i++) {
        int idx = i * 256 + tid;
        int kl = idx >> 6, nl = idx & 63;
        sN[kl][nl] = Wb[(size_t)(k0 + kl) * HIDDEN + n0 + nl];
    }
    __syncthreads();
    unsigned short* HI = (KD == KAUG) ? g_b1hi : g_b2hi;
    unsigned short* LO = (KD == KAUG) ? g_b1lo : g_b2lo;
#pragma unroll
    for (int j = 0; j < 2; j++) {
        int u = j * 256 + tid;
        int nl = u >> 3, g = u & 7;
        uint32_t hw[4], lw[4];
#pragma unroll
        for (int q = 0; q < 4; q++) {
            unsigned short h0, l0, h1, l1;
            split2(sN[g*8 + 2*q][nl],     h0, l0);
            split2(sN[g*8 + 2*q + 1][nl], h1, l1);
            hw[q] = (uint32_t)h0 | ((uint32_t)h1 << 16);
            lw[q] = (uint32_t)l0 | ((uint32_t)l1 << 16);
        }
        size_t o = ((size_t)e * HIDDEN + n0 + nl) * KD + k0 + g * 8;
        *(uint4*)&HI[o] = make_uint4(hw[0], hw[1], hw[2], hw[3]);
        *(uint4*)&LO[o] = make_uint4(lw[0], lw[1], lw[2], lw[3]);
    }
}

// ---------------- grouped GEMM: mma.sync bf16, K_eff = 3*K (hh, hl, lh) ----------------
// CTA 128x128, BK=32, 4-stage cp.async, 8 warps (2M x 4N), warp tile 64x32
template <int LAYER>
__global__ __launch_bounds__(256, 2)
void k_gemm(const float* __restrict__ bias, float* __restrict__ out) {
    constexpr int KD  = (LAYER == 1) ? KAUG : HIDDEN;
    constexpr int CPT = KD / 32;          // chunks per term
    constexpr int NCH = 3 * CPT;

    const int e = blockIdx.z;
    const int cnt = g_cnt[e];
    const int m0 = blockIdx.x << 7;
    if (m0 >= cnt) return;
    const int off = g_off[e];
    const int nb = blockIdx.y;            // n-tile (128 wide)
    const int slot = g_tilebase[e] + (m0 >> 7);

    extern __shared__ unsigned char smraw[];
    const uint32_t smb = smem_u32(smraw);

    const int tid = threadIdx.x;
    const int lane = tid & 31, wid = tid >> 5;
    const int wm = (wid & 1) * 64;        // warp M origin
    const int wn = (wid >> 1) * 32;       // warp N origin

    const unsigned short* Ahi = (LAYER == 1) ? g_ahi : g_hhi;
    const unsigned short* Alo = (LAYER == 1) ? g_alo : g_hlo;
    const unsigned short* Bhi = (LAYER == 1) ? g_b1hi : g_b2hi;
    const unsigned short* Blo = (LAYER == 1) ? g_b1lo : g_b2lo;
    const size_t arow0 = (size_t)slot * 128 * KD;
    const size_t brow0 = ((size_t)e * HIDDEN + nb * 128) * (size_t)KD;

    // ---- async loader: chunk c -> stage st ----
    auto load = [&](int c, int st) {
        const int term = c / CPT;
        const int kk = (c - term * CPT) * 32;
        const unsigned short* Ag = ((term == 2) ? Alo : Ahi) + arow0 + kk;
        const unsigned short* Bg = ((term == 1) ? Blo : Bhi) + brow0 + kk;
        const uint32_t sA = smb + st * STAGEB;
        const uint32_t sB = sA + TILEB;
#pragma unroll
        for (int u = tid; u < 512; u += 256) {       // 128 rows x 4 segs of 16B
            const int row = u >> 2, seg = u & 3;
            cp16(sA + row * ROWB + seg * 16, Ag + (size_t)row * KD + seg * 8);
            cp16(sB + row * ROWB + seg * 16, Bg + (size_t)row * KD + seg * 8);
        }
    };

    // ldmatrix lane addressing (lanes 0-15 rows/k0, 16-31 rows/k8)
    const int lrow = lane & 15;
    const int lsegB = (lane >> 4) * 16;
    uint32_t aoff[4], boff[2];
#pragma unroll
    for (int mi = 0; mi < 4; mi++) aoff[mi] = (wm + mi * 16 + lrow) * ROWB + lsegB;
#pragma unroll
    for (int nj = 0; nj < 2; nj++) boff[nj] = (wn + nj * 16 + lrow) * ROWB + lsegB;

    float acc[4][4][4];
#pragma unroll
    for (int mi = 0; mi < 4; mi++)
#pragma unroll
        for (int ni = 0; ni < 4; ni++)
#pragma unroll
            for (int r = 0; r < 4; r++) acc[mi][ni][r] = 0.f;

    // prologue
#pragma unroll
    for (int c = 0; c < STAGES - 1; c++) { load(c, c); cp_commit(); }

    for (int c = 0; c < NCH; c++) {
        cp_wait<STAGES - 2>();
        __syncthreads();
        if (c + STAGES - 1 < NCH) load(c + STAGES - 1, (c + STAGES - 1) & (STAGES - 1));
        cp_commit();

        const uint32_t sA = smb + (c & (STAGES - 1)) * STAGEB;
        const uint32_t sB = sA + TILEB;
#pragma unroll
        for (int ks = 0; ks < 2; ks++) {
            const int kb = ks * 32;
            uint32_t a[4][4], b[2][4];
#pragma unroll
            for (int mi = 0; mi < 4; mi++) ldm4(a[mi], sA + aoff[mi] + kb);
#pragma unroll
            for (int nj = 0; nj < 2; nj++) ldm4(b[nj], sB + boff[nj] + kb);
#pragma unroll
            for (int mi = 0; mi < 4; mi++)
#pragma unroll
                for (int nj = 0; nj < 2; nj++) {
                    mma16816(acc[mi][nj*2+0], a[mi], b[nj][0], b[nj][2]);
                    mma16816(acc[mi][nj*2+1], a[mi], b[nj][1], b[nj][3]);
                }
        }
    }
    cp_wait<0>();

    // ---- epilogue: bias + relu; L1 -> split to h hi/lo; L2 -> scatter to out ----
    const int mb = lane >> 2;             // row within 8
    const int nb2 = (lane & 3) * 2;       // col pair within 8
    const int nbase = nb * 128 + wn;

#pragma unroll
    for (int mi = 0; mi < 4; mi++) {
#pragma unroll
        for (int half = 0; half < 2; half++) {      // row, row+8
            const int r = wm + mi * 16 + mb + half * 8;
            if (LAYER == 2) {
                if (m0 + r >= cnt) continue;
                const int t = g_idx[off + m0 + r];
                float* dst = out + (size_t)t * HIDDEN;
#pragma unroll
                for (int ni = 0; ni < 4; ni++) {
                    const int n = nbase + ni * 8 + nb2;
                    float v0 = fmaxf(acc[mi][ni][half*2+0] + __ldg(&bias[e*HIDDEN + n]),     0.f);
                    float v1 = fmaxf(acc[mi][ni][half*2+1] + __ldg(&bias[e*HIDDEN + n + 1]), 0.f);
                    *(float2*)(dst + n) = make_float2(v0, v1);
                }
            } else {
                const size_t hrow = ((size_t)slot * 128 + r) * HIDDEN;
#pragma unroll
                for (int ni = 0; ni < 4; ni++) {
                    const int n = nbase + ni * 8 + nb2;
                    float v0 = fmaxf(acc[mi][ni][half*2+0] + __ldg(&bias[e*HIDDEN + n]),     0.f);
                    float v1 = fmaxf(acc[mi][ni][half*2+1] + __ldg(&bias[e*HIDDEN + n + 1]), 0.f);
                    unsigned short h0, l0, h1, l1;
                    split2(v0, h0, l0);
                    split2(v1, h1, l1);
                    *(uint32_t*)&g_hhi[hrow + n] = (uint32_t)h0 | ((uint32_t)h1 << 16);
                    *(uint32_t*)&g_hlo[hrow + n] = (uint32_t)l0 | ((uint32_t)l1 << 16);
                }
            }
        }
    }
}

// ---------------- launch ----------------
extern "C" void kernel_launch(void* const* d_in, const int* in_sizes, int n_in,
                              void* d_out, int out_size)
{
    const float* x      = (const float*)d_in[0];
    const int*   ops    = (const int*)  d_in[1];
    const float* op_emb = (const float*)d_in[2];
    const float* W1     = (const float*)d_in[3];
    const float* b1     = (const float*)d_in[4];
    const float* W2     = (const float*)d_in[5];
    const float* b2     = (const float*)d_in[6];
    float* out = (float*)d_out;

    cudaFuncSetAttribute(k_gemm<1>, cudaFuncAttributeMaxDynamicSharedMemorySize, SMEM_GEMM);
    cudaFuncSetAttribute(k_gemm<2>, cudaFuncAttributeMaxDynamicSharedMemorySize, SMEM_GEMM);

    k_zero<<<1, 32>>>();
    k_count<<<BATCH / 256, 256>>>(ops);
    k_scan<<<1, 1>>>();
    k_scatter<<<BATCH / 256, 256>>>(ops);

    k_aconv<<<MAXS, 256>>>(x, op_emb);
    k_wconv<KAUG>  <<<dim3(KAUG / 64, 16, NOPS), 256>>>(W1);
    k_wconv<HIDDEN><<<dim3(HIDDEN / 64, 16, NOPS), 256>>>(W2);

    dim3 grid(BATCH / 128, HIDDEN / 128, NOPS);   // early-exit prunes unused m-tiles
    k_gemm<1><<<grid, 256, SMEM_GEMM>>>(b1, nullptr);
    k_gemm<2><<<grid, 256, SMEM_GEMM>>>(b2, out);
}